// round 5
// baseline (speedup 1.0000x reference)
#include <cuda_runtime.h>

// x: [2, 64, 64, 96, 96] fp32. NSEQ = 128 sequences of T = 64, HID = 4.
#define NBLK   296u          // 2 blocks per SM on 148+ SMs -> all co-resident
#define NTHR   256
#define NWARPS 2368u         // NBLK * 8
#define NROWS  8192u         // bs*c*d
#define NV     18874368u     // total float4 vectors
#define STRIDE 75776u        // NBLK * NTHR
#define TSTEPS 64

__device__ float g_mean[8192];       // [seq][t]
__device__ float g_last[128 * 8];    // [seq][fwd h(4) | bwd h(4)]
__device__ float g_scale[128];
__device__ unsigned g_arr1, g_arr2, g_done, g_exit;   // zero-init, self-reset

__device__ __forceinline__ float tanh_ap(float x) {
    float y;
    asm("tanh.approx.f32 %0, %1;" : "=f"(y) : "f"(x));
    return y;
}
__device__ __forceinline__ float sig_ap(float x) {
    return fmaf(0.5f, tanh_ap(0.5f * x), 0.5f);
}
__device__ __forceinline__ float sig_acc(float x) {
    return __fdividef(1.f, 1.f + __expf(-x));
}

__global__ __launch_bounds__(NTHR, 2) void fused_kernel(
    const float* __restrict__ x,
    const float* __restrict__ wih0f, const float* __restrict__ whh0f,
    const float* __restrict__ bih0f, const float* __restrict__ bhh0f,
    const float* __restrict__ wih0b, const float* __restrict__ whh0b,
    const float* __restrict__ bih0b, const float* __restrict__ bhh0b,
    const float* __restrict__ wih1f, const float* __restrict__ whh1f,
    const float* __restrict__ bih1f, const float* __restrict__ bhh1f,
    const float* __restrict__ wih1b, const float* __restrict__ whh1b,
    const float* __restrict__ bih1b, const float* __restrict__ bhh1b,
    const float* __restrict__ w1,    const float* __restrict__ w2,
    float* __restrict__ out) {
    __shared__ float s_mean[256];
    __shared__ float s_h0[4][516];
    __shared__ float z[1024];
    __shared__ float h1s[64];
    __shared__ float s_scale[128];
    __shared__ unsigned s_flag;

    const int tid = threadIdx.x;
    const int lane = tid & 31;

    // ================= Phase A: spatial means (warp per row) ================
    {
        unsigned gw = (blockIdx.x * (unsigned)NTHR + tid) >> 5;
        for (unsigned r = gw; r < NROWS; r += NWARPS) {
            const float4* p = reinterpret_cast<const float4*>(x) + (size_t)r * 2304u;
            float s0 = 0.f, s1 = 0.f, s2 = 0.f, s3 = 0.f;
#pragma unroll
            for (int i = 0; i < 72; i += 8) {
                float4 a0 = p[lane + (i + 0) * 32];
                float4 a1 = p[lane + (i + 1) * 32];
                float4 a2 = p[lane + (i + 2) * 32];
                float4 a3 = p[lane + (i + 3) * 32];
                float4 a4 = p[lane + (i + 4) * 32];
                float4 a5 = p[lane + (i + 5) * 32];
                float4 a6 = p[lane + (i + 6) * 32];
                float4 a7 = p[lane + (i + 7) * 32];
                s0 += (a0.x + a0.y) + (a0.z + a0.w);
                s1 += (a1.x + a1.y) + (a1.z + a1.w);
                s2 += (a2.x + a2.y) + (a2.z + a2.w);
                s3 += (a3.x + a3.y) + (a3.z + a3.w);
                s0 += (a4.x + a4.y) + (a4.z + a4.w);
                s1 += (a5.x + a5.y) + (a5.z + a5.w);
                s2 += (a6.x + a6.y) + (a6.z + a6.w);
                s3 += (a7.x + a7.y) + (a7.z + a7.w);
            }
            float s = (s0 + s1) + (s2 + s3);
#pragma unroll
            for (int off = 16; off > 0; off >>= 1)
                s += __shfl_down_sync(0xffffffffu, s, off);
            if (lane == 0) g_mean[r] = s * (1.f / 9216.f);
        }
    }
    __threadfence();
    __syncthreads();
    if (tid == 0) atomicAdd(&g_arr1, 1u);

    // ================= Phase B: biLSTM + SE MLP (blocks 0..31, warp 0) ======
    if (blockIdx.x < 32u && tid < 32) {
        int j   = tid & 3;
        int u   = tid >> 2;
        int sl  = u >> 1;
        int dir = u & 1;

        // register-load weights BEFORE the barrier spin (overlaps the wait)
        const float* WIH0 = dir ? wih0b : wih0f;
        const float* WHH0 = dir ? whh0b : whh0f;
        const float* BI0  = dir ? bih0b : bih0f;
        const float* BH0  = dir ? bhh0b : bhh0f;
        float w_ih0[4], w_hh0[16], b0[4];
#pragma unroll
        for (int g = 0; g < 4; ++g) {
            int k = g * 4 + j;
            w_ih0[g] = WIH0[k];
            b0[g]    = BI0[k] + BH0[k];
#pragma unroll
            for (int m = 0; m < 4; ++m) w_hh0[g * 4 + m] = WHH0[k * 4 + m];
        }
        const float* WIH1 = (tid < 16) ? wih1f : wih1b;
        const float* WHH1 = (tid < 16) ? whh1f : whh1b;
        const float* BI1  = (tid < 16) ? bih1f : bih1b;
        const float* BH1  = (tid < 16) ? bhh1f : bhh1b;
        int j1 = tid & 3;
        float w1i[32], w1h[16], b1[4];
#pragma unroll
        for (int g = 0; g < 4; ++g) {
            int k = g * 4 + j1;
            b1[g] = BI1[k] + BH1[k];
#pragma unroll
            for (int m = 0; m < 8; ++m) w1i[g * 8 + m] = WIH1[k * 8 + m];
#pragma unroll
            for (int m = 0; m < 4; ++m) w1h[g * 4 + m] = WHH1[k * 4 + m];
        }

        // wait for all means
        if (tid == 0) {
            while (*(volatile unsigned*)&g_arr1 != NBLK) __nanosleep(64);
        }
        __syncwarp();
        __threadfence();  // acquire

#pragma unroll
        for (int i = 0; i < 8; ++i)
            s_mean[tid + i * 32] = __ldcg(&g_mean[blockIdx.x * 256u + tid + i * 32]);
        __syncwarp();

        // ---------------- layer 0 ----------------
        {
            float hj = 0.f, cj = 0.f;
            const float* mrow = s_mean + sl * 64;
            float* hrow = s_h0[sl];
            int foff = dir * 4 + j;
            for (int st = 0; st < TSTEPS; ++st) {
                int t = dir ? (TSTEPS - 1 - st) : st;
                float xt = mrow[t];
                float h0 = __shfl_sync(0xffffffffu, hj, 0, 4);
                float h1 = __shfl_sync(0xffffffffu, hj, 1, 4);
                float h2 = __shfl_sync(0xffffffffu, hj, 2, 4);
                float h3 = __shfl_sync(0xffffffffu, hj, 3, 4);
                float ga[4];
#pragma unroll
                for (int g = 0; g < 4; ++g) {
                    float p0 = fmaf(w_ih0[g], xt, b0[g]);
                    p0 = fmaf(w_hh0[g * 4 + 0], h0, p0);
                    float p1 = fmaf(w_hh0[g * 4 + 2], h2, w_hh0[g * 4 + 1] * h1);
                    float p2 = w_hh0[g * 4 + 3] * h3;
                    ga[g] = p0 + (p1 + p2);
                }
                float ig = sig_ap(ga[0]), fg = sig_ap(ga[1]);
                float gg = tanh_ap(ga[2]), og = sig_ap(ga[3]);
                cj = fmaf(fg, cj, ig * gg);
                hj = og * tanh_ap(cj);
                hrow[t * 8 + foff] = hj;
            }
        }
        __syncwarp();

        // ---------------- layer 1 ----------------
        if (tid < 16) {
            int s1 = tid >> 2;
            const float* hrow = s_h0[s1];
            float hj = 0.f, cj = 0.f;
            for (int t = 0; t < TSTEPS; ++t) {
                float4 xa = *reinterpret_cast<const float4*>(hrow + t * 8);
                float4 xb = *reinterpret_cast<const float4*>(hrow + t * 8 + 4);
                float h0 = __shfl_sync(0x0000ffffu, hj, 0, 4);
                float h1 = __shfl_sync(0x0000ffffu, hj, 1, 4);
                float h2 = __shfl_sync(0x0000ffffu, hj, 2, 4);
                float h3 = __shfl_sync(0x0000ffffu, hj, 3, 4);
                float ga[4];
#pragma unroll
                for (int g = 0; g < 4; ++g) {
                    const float* wi = w1i + g * 8;
                    const float* wh = w1h + g * 4;
                    float p0 = fmaf(wi[0], xa.x, b1[g]);
                    p0 = fmaf(wi[1], xa.y, p0);
                    float p1 = fmaf(wi[3], xa.w, wi[2] * xa.z);
                    float p2 = fmaf(wi[5], xb.y, wi[4] * xb.x);
                    float p3 = fmaf(wi[7], xb.w, wi[6] * xb.z);
                    float p4 = fmaf(wh[1], h1, wh[0] * h0);
                    float p5 = fmaf(wh[3], h3, wh[2] * h2);
                    ga[g] = ((p0 + p1) + (p2 + p3)) + (p4 + p5);
                }
                float ig = sig_ap(ga[0]), fg = sig_ap(ga[1]);
                float gg = tanh_ap(ga[2]), og = sig_ap(ga[3]);
                cj = fmaf(fg, cj, ig * gg);
                hj = og * tanh_ap(cj);
            }
            g_last[(blockIdx.x * 4 + s1) * 8 + j1] = hj;
        } else {
            int s1 = (tid - 16) >> 2;
            const float* hrow = s_h0[s1];
            float4 xa = *reinterpret_cast<const float4*>(hrow + (TSTEPS - 1) * 8);
            float4 xb = *reinterpret_cast<const float4*>(hrow + (TSTEPS - 1) * 8 + 4);
            float ga[4];
#pragma unroll
            for (int g = 0; g < 4; ++g) {
                const float* wi = w1i + g * 8;
                float p0 = fmaf(wi[0], xa.x, b1[g]);
                p0 = fmaf(wi[1], xa.y, p0);
                float p1 = fmaf(wi[3], xa.w, wi[2] * xa.z);
                float p2 = fmaf(wi[5], xb.y, wi[4] * xb.x);
                float p3 = fmaf(wi[7], xb.w, wi[6] * xb.z);
                ga[g] = (p0 + p1) + (p2 + p3);
            }
            float cj = sig_ap(ga[0]) * tanh_ap(ga[2]);
            float hj = sig_ap(ga[3]) * tanh_ap(cj);
            g_last[(blockIdx.x * 4 + s1) * 8 + 4 + j1] = hj;
        }

        // last lstm block runs the SE MLP
        __threadfence();
        if (tid == 0) s_flag = (atomicAdd(&g_arr2, 1u) == 31u) ? 1u : 0u;
        __syncwarp();
        if (s_flag) {
            __threadfence();  // acquire other blocks' g_last
            for (int k = tid; k < 1024; k += 32) z[k] = __ldcg(&g_last[k]);
            __syncwarp();
            {
                const float* wr = w1 + tid * 512;
                float a0 = 0, a1 = 0, a2 = 0, a3 = 0;
                float c0 = 0, c1 = 0, c2 = 0, c3 = 0;
#pragma unroll 4
                for (int k = 0; k < 512; k += 4) {
                    float wk0 = wr[k], wk1 = wr[k + 1], wk2 = wr[k + 2], wk3 = wr[k + 3];
                    a0 = fmaf(wk0, z[k], a0);       a1 = fmaf(wk1, z[k + 1], a1);
                    a2 = fmaf(wk2, z[k + 2], a2);   a3 = fmaf(wk3, z[k + 3], a3);
                    c0 = fmaf(wk0, z[512 + k], c0); c1 = fmaf(wk1, z[513 + k], c1);
                    c2 = fmaf(wk2, z[514 + k], c2); c3 = fmaf(wk3, z[515 + k], c3);
                }
                h1s[tid]      = fmaxf((a0 + a1) + (a2 + a3), 0.f);
                h1s[32 + tid] = fmaxf((c0 + c1) + (c2 + c3), 0.f);
            }
            __syncwarp();
#pragma unroll
            for (int i = 0; i < 4; ++i) {
                int idx = tid + i * 32;
                int b = idx >> 6, ch = idx & 63;
                const float* wr = w2 + ch * 32;
                const float* hb = h1s + b * 32;
                float acc = 0.f;
#pragma unroll
                for (int m = 0; m < 32; ++m) acc = fmaf(wr[m], hb[m], acc);
                g_scale[idx] = sig_acc(acc);
            }
            __syncwarp();
            __threadfence();
            if (tid == 0) atomicExch(&g_done, 1u);
        }
    }

    // ================= Phase C: out = x * scale =============================
    unsigned v = blockIdx.x * (unsigned)NTHR + tid;
    const float4* px = reinterpret_cast<const float4*>(x);
    float4* po = reinterpret_cast<float4*>(out);

    // prefetch first 4 iterations' loads; they fly while we wait on g_done
    float4 pf0 = __ldcs(px + v);
    float4 pf1 = __ldcs(px + v + STRIDE);
    float4 pf2 = __ldcs(px + v + 2u * STRIDE);
    float4 pf3 = __ldcs(px + v + 3u * STRIDE);

    if (tid == 32) {
        while (*(volatile unsigned*)&g_done == 0u) __nanosleep(128);
        __threadfence();
    }
    __syncthreads();
    if (tid < 128) s_scale[tid] = __ldcg(&g_scale[tid]);
    __syncthreads();

    {
        float sc;
        sc = s_scale[v / 147456u];
        pf0.x *= sc; pf0.y *= sc; pf0.z *= sc; pf0.w *= sc;
        __stcs(po + v, pf0); v += STRIDE;
        sc = s_scale[v / 147456u];
        pf1.x *= sc; pf1.y *= sc; pf1.z *= sc; pf1.w *= sc;
        __stcs(po + v, pf1); v += STRIDE;
        sc = s_scale[v / 147456u];
        pf2.x *= sc; pf2.y *= sc; pf2.z *= sc; pf2.w *= sc;
        __stcs(po + v, pf2); v += STRIDE;
        sc = s_scale[v / 147456u];
        pf3.x *= sc; pf3.y *= sc; pf3.z *= sc; pf3.w *= sc;
        __stcs(po + v, pf3); v += STRIDE;
    }
    while (v + 3u * STRIDE < NV) {
        float4 t0 = __ldcs(px + v);
        float4 t1 = __ldcs(px + v + STRIDE);
        float4 t2 = __ldcs(px + v + 2u * STRIDE);
        float4 t3 = __ldcs(px + v + 3u * STRIDE);
        float s0 = s_scale[v / 147456u];
        float s1 = s_scale[(v + STRIDE) / 147456u];
        float s2 = s_scale[(v + 2u * STRIDE) / 147456u];
        float s3 = s_scale[(v + 3u * STRIDE) / 147456u];
        t0.x *= s0; t0.y *= s0; t0.z *= s0; t0.w *= s0;
        t1.x *= s1; t1.y *= s1; t1.z *= s1; t1.w *= s1;
        t2.x *= s2; t2.y *= s2; t2.z *= s2; t2.w *= s2;
        t3.x *= s3; t3.y *= s3; t3.z *= s3; t3.w *= s3;
        __stcs(po + v, t0);
        __stcs(po + v + STRIDE, t1);
        __stcs(po + v + 2u * STRIDE, t2);
        __stcs(po + v + 3u * STRIDE, t3);
        v += 4u * STRIDE;
    }
    while (v < NV) {
        float4 t = __ldcs(px + v);
        float sc = s_scale[v / 147456u];
        t.x *= sc; t.y *= sc; t.z *= sc; t.w *= sc;
        __stcs(po + v, t);
        v += STRIDE;
    }

    // ================= epilogue: self-reset counters for graph replay ======
    __syncthreads();
    if (tid == 0) {
        unsigned r = atomicAdd(&g_exit, 1u);
        if (r == NBLK - 1u) {
            g_arr1 = 0u;
            g_arr2 = 0u;
            g_done = 0u;
            g_exit = 0u;
        }
    }
}

extern "C" void kernel_launch(void* const* d_in, const int* in_sizes, int n_in,
                              void* d_out, int out_size) {
    fused_kernel<<<NBLK, NTHR>>>(
        (const float*)d_in[0],
        (const float*)d_in[1],  (const float*)d_in[2],
        (const float*)d_in[3],  (const float*)d_in[4],
        (const float*)d_in[5],  (const float*)d_in[6],
        (const float*)d_in[7],  (const float*)d_in[8],
        (const float*)d_in[9],  (const float*)d_in[10],
        (const float*)d_in[11], (const float*)d_in[12],
        (const float*)d_in[13], (const float*)d_in[14],
        (const float*)d_in[15], (const float*)d_in[16],
        (const float*)d_in[17], (const float*)d_in[18],
        (float*)d_out);
}

// round 6
// speedup vs baseline: 1.5110x; 1.5110x over previous
#include <cuda_runtime.h>

// Problem constants: x [2, 64, 64, 96, 96]; NSEQ = bs*c = 128; T = d = 64; HID = 4
#define NSEQ 128
#define TSTEPS 64
#define ROWVEC 2304          // 96*96/4

__device__ float g_mean[NSEQ * TSTEPS];   // [seq=b*64+c][t=d]
__device__ float g_last[NSEQ * 8];        // last-timestep [fwd h(4) | bwd h(4)]
__device__ float g_scale[NSEQ];           // sigmoid output per (b,c)
__device__ unsigned g_ctr;                // last-block counter (self-resetting)

__device__ __forceinline__ void gdc_wait() {
    asm volatile("griddepcontrol.wait;" ::: "memory");
}

__device__ __forceinline__ float tanh_ap(float x) {
    float y;
    asm("tanh.approx.f32 %0, %1;" : "=f"(y) : "f"(x));
    return y;
}
__device__ __forceinline__ float sig_ap(float x) {
    return fmaf(0.5f, tanh_ap(0.5f * x), 0.5f);
}
__device__ __forceinline__ float sig_acc(float x) {
    return __fdividef(1.f, 1.f + __expf(-x));
}

// ---------------------------------------------------------------------------
// Kernel 1: mean over H,W for each (b,c,d) row. One block per row.
// ---------------------------------------------------------------------------
__global__ void mean_kernel(const float* __restrict__ x) {
    int r = blockIdx.x;
    const float4* p = reinterpret_cast<const float4*>(x) + (size_t)r * ROWVEC;
    float4 v[9];
#pragma unroll
    for (int i = 0; i < 9; ++i) v[i] = p[threadIdx.x + i * 256];
    float s = 0.f;
#pragma unroll
    for (int i = 0; i < 9; ++i) s += (v[i].x + v[i].y) + (v[i].z + v[i].w);
#pragma unroll
    for (int off = 16; off > 0; off >>= 1)
        s += __shfl_down_sync(0xffffffffu, s, off);
    __shared__ float red[8];
    int warp = threadIdx.x >> 5, lane = threadIdx.x & 31;
    if (lane == 0) red[warp] = s;
    __syncthreads();
    if (threadIdx.x < 8) {
        s = red[threadIdx.x];
        s += __shfl_down_sync(0xffu, s, 4);
        s += __shfl_down_sync(0xffu, s, 2);
        s += __shfl_down_sync(0xffu, s, 1);
        if (threadIdx.x == 0) g_mean[r] = s * (1.f / 9216.f);
    }
}

// ---------------------------------------------------------------------------
// Kernel 2: 2-layer biLSTM (hidden=4), 4 threads per cell, tanh.approx
// activations. 32 blocks x 32 threads; block covers 4 sequences.
// PDL: weights are register-loaded BEFORE griddepcontrol.wait, so the loads
// overlap the tail of mean_kernel. The last block also runs the SE MLP.
// ---------------------------------------------------------------------------
__global__ void lstm_kernel(
    const float* __restrict__ wih0f, const float* __restrict__ whh0f,
    const float* __restrict__ bih0f, const float* __restrict__ bhh0f,
    const float* __restrict__ wih0b, const float* __restrict__ whh0b,
    const float* __restrict__ bih0b, const float* __restrict__ bhh0b,
    const float* __restrict__ wih1f, const float* __restrict__ whh1f,
    const float* __restrict__ bih1f, const float* __restrict__ bhh1f,
    const float* __restrict__ wih1b, const float* __restrict__ whh1b,
    const float* __restrict__ bih1b, const float* __restrict__ bhh1b,
    const float* __restrict__ w1,    const float* __restrict__ w2) {
    __shared__ float s_mean[256];      // 4 seqs x 64 t
    __shared__ float s_h0[4][516];     // 4 seqs x (64 t x 8 feat) + pad

    int tid = threadIdx.x;
    int j   = tid & 3;        // cell index within hidden=4
    int u   = tid >> 2;       // unit 0..7
    int sl  = u >> 1;         // local seq 0..3
    int dir = u & 1;

    // ---- register-load layer-0 weights BEFORE the dependency wait ----
    const float* WIH0 = dir ? wih0b : wih0f;
    const float* WHH0 = dir ? whh0b : whh0f;
    const float* BI0  = dir ? bih0b : bih0f;
    const float* BH0  = dir ? bhh0b : bhh0f;
    float w_ih0[4], w_hh0[16], b0[4];
#pragma unroll
    for (int g = 0; g < 4; ++g) {
        int k = g * 4 + j;
        w_ih0[g] = WIH0[k];
        b0[g]    = BI0[k] + BH0[k];
#pragma unroll
        for (int m = 0; m < 4; ++m) w_hh0[g * 4 + m] = WHH0[k * 4 + m];
    }
    const float* WIH1 = (tid < 16) ? wih1f : wih1b;
    const float* WHH1 = (tid < 16) ? whh1f : whh1b;
    const float* BI1  = (tid < 16) ? bih1f : bih1b;
    const float* BH1  = (tid < 16) ? bhh1f : bhh1b;
    int j1 = tid & 3;
    float w1i[32], w1h[16], b1[4];
#pragma unroll
    for (int g = 0; g < 4; ++g) {
        int k = g * 4 + j1;
        b1[g] = BI1[k] + BH1[k];
#pragma unroll
        for (int m = 0; m < 8; ++m) w1i[g * 8 + m] = WIH1[k * 8 + m];
#pragma unroll
        for (int m = 0; m < 4; ++m) w1h[g * 4 + m] = WHH1[k * 4 + m];
    }

    // ---- wait for mean_kernel completion (implicit trigger) ----
    gdc_wait();

#pragma unroll
    for (int i = 0; i < 8; ++i)
        s_mean[tid + i * 32] = g_mean[blockIdx.x * 256 + tid + i * 32];
    __syncwarp();

    // ---------------- layer 0 ----------------
    {
        float hj = 0.f, cj = 0.f;
        const float* mrow = s_mean + sl * 64;
        float* hrow = s_h0[sl];
        int foff = dir * 4 + j;
        for (int st = 0; st < TSTEPS; ++st) {
            int t = dir ? (TSTEPS - 1 - st) : st;
            float xt = mrow[t];
            float h0 = __shfl_sync(0xffffffffu, hj, 0, 4);
            float h1 = __shfl_sync(0xffffffffu, hj, 1, 4);
            float h2 = __shfl_sync(0xffffffffu, hj, 2, 4);
            float h3 = __shfl_sync(0xffffffffu, hj, 3, 4);
            float ga[4];
#pragma unroll
            for (int g = 0; g < 4; ++g) {
                float p0 = fmaf(w_ih0[g], xt, b0[g]);
                p0 = fmaf(w_hh0[g * 4 + 0], h0, p0);
                float p1 = fmaf(w_hh0[g * 4 + 2], h2, w_hh0[g * 4 + 1] * h1);
                float p2 = w_hh0[g * 4 + 3] * h3;
                ga[g] = p0 + (p1 + p2);
            }
            float ig = sig_ap(ga[0]), fg = sig_ap(ga[1]);
            float gg = tanh_ap(ga[2]), og = sig_ap(ga[3]);
            cj = fmaf(fg, cj, ig * gg);
            hj = og * tanh_ap(cj);
            hrow[t * 8 + foff] = hj;
        }
    }
    __syncwarp();

    // ---------------- layer 1 ----------------
    if (tid < 16) {
        int s1 = tid >> 2;
        const float* hrow = s_h0[s1];
        float hj = 0.f, cj = 0.f;
        for (int t = 0; t < TSTEPS; ++t) {
            float4 xa = *reinterpret_cast<const float4*>(hrow + t * 8);
            float4 xb = *reinterpret_cast<const float4*>(hrow + t * 8 + 4);
            float h0 = __shfl_sync(0x0000ffffu, hj, 0, 4);
            float h1 = __shfl_sync(0x0000ffffu, hj, 1, 4);
            float h2 = __shfl_sync(0x0000ffffu, hj, 2, 4);
            float h3 = __shfl_sync(0x0000ffffu, hj, 3, 4);
            float ga[4];
#pragma unroll
            for (int g = 0; g < 4; ++g) {
                const float* wi = w1i + g * 8;
                const float* wh = w1h + g * 4;
                float p0 = fmaf(wi[0], xa.x, b1[g]);
                p0 = fmaf(wi[1], xa.y, p0);
                float p1 = fmaf(wi[3], xa.w, wi[2] * xa.z);
                float p2 = fmaf(wi[5], xb.y, wi[4] * xb.x);
                float p3 = fmaf(wi[7], xb.w, wi[6] * xb.z);
                float p4 = fmaf(wh[1], h1, wh[0] * h0);
                float p5 = fmaf(wh[3], h3, wh[2] * h2);
                ga[g] = ((p0 + p1) + (p2 + p3)) + (p4 + p5);
            }
            float ig = sig_ap(ga[0]), fg = sig_ap(ga[1]);
            float gg = tanh_ap(ga[2]), og = sig_ap(ga[3]);
            cj = fmaf(fg, cj, ig * gg);
            hj = og * tanh_ap(cj);
        }
        g_last[(blockIdx.x * 4 + s1) * 8 + j1] = hj;
    } else {
        // backward: only the first processed step (original t = T-1) is used.
        int s1 = (tid - 16) >> 2;
        const float* hrow = s_h0[s1];
        float4 xa = *reinterpret_cast<const float4*>(hrow + (TSTEPS - 1) * 8);
        float4 xb = *reinterpret_cast<const float4*>(hrow + (TSTEPS - 1) * 8 + 4);
        float ga[4];
#pragma unroll
        for (int g = 0; g < 4; ++g) {
            const float* wi = w1i + g * 8;
            float p0 = fmaf(wi[0], xa.x, b1[g]);
            p0 = fmaf(wi[1], xa.y, p0);
            float p1 = fmaf(wi[3], xa.w, wi[2] * xa.z);
            float p2 = fmaf(wi[5], xb.y, wi[4] * xb.x);
            float p3 = fmaf(wi[7], xb.w, wi[6] * xb.z);
            ga[g] = (p0 + p1) + (p2 + p3);
        }
        float cj = sig_ap(ga[0]) * tanh_ap(ga[2]);
        float hj = sig_ap(ga[3]) * tanh_ap(cj);
        g_last[(blockIdx.x * 4 + s1) * 8 + 4 + j1] = hj;
    }

    // ---------------- fc (SE MLP) in the last-arriving block ----------------
    __syncwarp();
    __shared__ unsigned s_last;
    if (tid == 0) {
        __threadfence();
        s_last = (atomicAdd(&g_ctr, 1u) == 31u);
    }
    __syncwarp();
    if (!s_last) return;
    __threadfence();  // acquire: make other blocks' g_last stores visible

    __shared__ float z[1024];
    __shared__ float h1s[64];
    for (int k = tid; k < 1024; k += 32) z[k] = __ldcg(&g_last[k]);
    __syncwarp();
    {
        const float* wr = w1 + tid * 512;
        float a0 = 0, a1 = 0, a2 = 0, a3 = 0;   // b = 0
        float c0 = 0, c1 = 0, c2 = 0, c3 = 0;   // b = 1
#pragma unroll 4
        for (int k = 0; k < 512; k += 4) {
            float wk0 = wr[k], wk1 = wr[k + 1], wk2 = wr[k + 2], wk3 = wr[k + 3];
            a0 = fmaf(wk0, z[k], a0);       a1 = fmaf(wk1, z[k + 1], a1);
            a2 = fmaf(wk2, z[k + 2], a2);   a3 = fmaf(wk3, z[k + 3], a3);
            c0 = fmaf(wk0, z[512 + k], c0); c1 = fmaf(wk1, z[513 + k], c1);
            c2 = fmaf(wk2, z[514 + k], c2); c3 = fmaf(wk3, z[515 + k], c3);
        }
        h1s[tid]      = fmaxf((a0 + a1) + (a2 + a3), 0.f);
        h1s[32 + tid] = fmaxf((c0 + c1) + (c2 + c3), 0.f);
    }
    __syncwarp();
#pragma unroll
    for (int i = 0; i < 4; ++i) {
        int idx = tid + i * 32;          // 0..127 -> (b = idx>>6, ch = idx&63)
        int b = idx >> 6, ch = idx & 63;
        const float* wr = w2 + ch * 32;
        const float* hb = h1s + b * 32;
        float acc = 0.f;
#pragma unroll
        for (int m = 0; m < 32; ++m) acc = fmaf(wr[m], hb[m], acc);
        g_scale[idx] = sig_acc(acc);
    }
    if (tid == 0) g_ctr = 0;  // reset for next graph replay
}

// ---------------------------------------------------------------------------
// Kernel 3: out = x * scale[bc]. Block = 1024 consecutive float4s (all in one
// bc since 147456 % 1024 == 0). PDL: ALL x loads are issued before the
// dependency wait — the first wave's entire read stream overlaps the lstm.
// ---------------------------------------------------------------------------
__global__ void scale_kernel(const float* __restrict__ x,
                             float* __restrict__ out) {
    unsigned base = blockIdx.x * 1024u + threadIdx.x;
    const float4* px = reinterpret_cast<const float4*>(x);
    float4* po = reinterpret_cast<float4*>(out);
    float4 v0 = __ldcs(px + base);
    float4 v1 = __ldcs(px + base + 256);
    float4 v2 = __ldcs(px + base + 512);
    float4 v3 = __ldcs(px + base + 768);

    gdc_wait();  // lstm_kernel complete -> g_scale valid

    float sc = g_scale[blockIdx.x / 144u];   // 147456/1024 = 144 blocks per bc
    v0.x *= sc; v0.y *= sc; v0.z *= sc; v0.w *= sc;
    v1.x *= sc; v1.y *= sc; v1.z *= sc; v1.w *= sc;
    v2.x *= sc; v2.y *= sc; v2.z *= sc; v2.w *= sc;
    v3.x *= sc; v3.y *= sc; v3.z *= sc; v3.w *= sc;
    __stcs(po + base, v0);
    __stcs(po + base + 256, v1);
    __stcs(po + base + 512, v2);
    __stcs(po + base + 768, v3);
}

// ---------------------------------------------------------------------------
extern "C" void kernel_launch(void* const* d_in, const int* in_sizes, int n_in,
                              void* d_out, int out_size) {
    const float* x = (const float*)d_in[0];

    mean_kernel<<<8192, 256>>>(x);

    cudaLaunchAttribute attr[1];
    attr[0].id = cudaLaunchAttributeProgrammaticStreamSerialization;
    attr[0].val.programmaticStreamSerializationAllowed = 1;

    {
        cudaLaunchConfig_t cfg = {};
        cfg.gridDim = dim3(32, 1, 1);
        cfg.blockDim = dim3(32, 1, 1);
        cfg.attrs = attr;
        cfg.numAttrs = 1;
        cudaLaunchKernelEx(&cfg, lstm_kernel,
            (const float*)d_in[1],  (const float*)d_in[2],
            (const float*)d_in[3],  (const float*)d_in[4],
            (const float*)d_in[5],  (const float*)d_in[6],
            (const float*)d_in[7],  (const float*)d_in[8],
            (const float*)d_in[9],  (const float*)d_in[10],
            (const float*)d_in[11], (const float*)d_in[12],
            (const float*)d_in[13], (const float*)d_in[14],
            (const float*)d_in[15], (const float*)d_in[16],
            (const float*)d_in[17], (const float*)d_in[18]);
    }
    {
        cudaLaunchConfig_t cfg = {};
        cfg.gridDim = dim3(18432, 1, 1);
        cfg.blockDim = dim3(256, 1, 1);
        cfg.attrs = attr;
        cfg.numAttrs = 1;
        cudaLaunchKernelEx(&cfg, scale_kernel, x, (float*)d_out);
    }
}

// round 9
// speedup vs baseline: 1.5591x; 1.0319x over previous
#include <cuda_runtime.h>

// Problem constants: x [2, 64, 64, 96, 96]; NSEQ = bs*c = 128; T = d = 64; HID = 4
#define NSEQ 128
#define TSTEPS 64
#define ROWVEC 2304          // 96*96/4
#define VECS_PER_BC 147456   // 64*96*96/4

__device__ float g_mean[NSEQ * TSTEPS];            // [seq=b*64+c][t=d]
__device__ __align__(16) float g_last[NSEQ * 8];   // [seq][fwd h(4) | bwd h(4)]
__device__ float g_scale[NSEQ];                    // sigmoid output per (b,c)
__device__ unsigned g_ctr;                         // last-block counter

__device__ __forceinline__ float tanh_ap(float x) {
    float y;
    asm("tanh.approx.f32 %0, %1;" : "=f"(y) : "f"(x));
    return y;
}
__device__ __forceinline__ float sig_ap(float x) {
    return fmaf(0.5f, tanh_ap(0.5f * x), 0.5f);
}
__device__ __forceinline__ float sig_acc(float x) {
    return __fdividef(1.f, 1.f + __expf(-x));
}

// ---------------------------------------------------------------------------
// Kernel 1: mean over H,W for each (b,c,d) row. One block per row.
// ---------------------------------------------------------------------------
__global__ void mean_kernel(const float* __restrict__ x) {
    int r = blockIdx.x;
    const float4* p = reinterpret_cast<const float4*>(x) + (size_t)r * ROWVEC;
    float4 v[9];
#pragma unroll
    for (int i = 0; i < 9; ++i) v[i] = p[threadIdx.x + i * 256];
    float s = 0.f;
#pragma unroll
    for (int i = 0; i < 9; ++i) s += (v[i].x + v[i].y) + (v[i].z + v[i].w);
#pragma unroll
    for (int off = 16; off > 0; off >>= 1)
        s += __shfl_down_sync(0xffffffffu, s, off);
    __shared__ float red[8];
    int warp = threadIdx.x >> 5, lane = threadIdx.x & 31;
    if (lane == 0) red[warp] = s;
    __syncthreads();
    if (threadIdx.x < 8) {
        s = red[threadIdx.x];
        s += __shfl_down_sync(0xffu, s, 4);
        s += __shfl_down_sync(0xffu, s, 2);
        s += __shfl_down_sync(0xffu, s, 1);
        if (threadIdx.x == 0) g_mean[r] = s * (1.f / 9216.f);
    }
}

// ---------------------------------------------------------------------------
// Kernel 2: 2-layer biLSTM (hidden=4), 4 threads per cell, tanh.approx
// activations. 32 blocks x 32 threads; block covers 4 sequences.
// The last-arriving block also runs the SE MLP with coalesced scalar loads
// of w1/w2. All SMEM arrays touched as float4 are explicitly 16B-aligned.
// ---------------------------------------------------------------------------
__global__ void lstm_kernel(
    const float* __restrict__ wih0f, const float* __restrict__ whh0f,
    const float* __restrict__ bih0f, const float* __restrict__ bhh0f,
    const float* __restrict__ wih0b, const float* __restrict__ whh0b,
    const float* __restrict__ bih0b, const float* __restrict__ bhh0b,
    const float* __restrict__ wih1f, const float* __restrict__ whh1f,
    const float* __restrict__ bih1f, const float* __restrict__ bhh1f,
    const float* __restrict__ wih1b, const float* __restrict__ whh1b,
    const float* __restrict__ bih1b, const float* __restrict__ bhh1b,
    const float* __restrict__ w1,    const float* __restrict__ w2) {
    __shared__ float s_mean[256];                     // 4 seqs x 64 t
    __shared__ __align__(16) float s_h0[4][516];      // 4 x (64 t x 8) + pad

    int tid = threadIdx.x;
    int j   = tid & 3;        // cell index within hidden=4
    int u   = tid >> 2;       // unit 0..7
    int sl  = u >> 1;         // local seq 0..3
    int dir = u & 1;

    // ---- register-load layer-0 weights (rows j, 4+j, 8+j, 12+j) ----
    const float* WIH0 = dir ? wih0b : wih0f;
    const float* WHH0 = dir ? whh0b : whh0f;
    const float* BI0  = dir ? bih0b : bih0f;
    const float* BH0  = dir ? bhh0b : bhh0f;
    float w_ih0[4], w_hh0[16], b0[4];
#pragma unroll
    for (int g = 0; g < 4; ++g) {
        int k = g * 4 + j;
        w_ih0[g] = WIH0[k];
        b0[g]    = BI0[k] + BH0[k];
#pragma unroll
        for (int m = 0; m < 4; ++m) w_hh0[g * 4 + m] = WHH0[k * 4 + m];
    }
    const float* WIH1 = (tid < 16) ? wih1f : wih1b;
    const float* WHH1 = (tid < 16) ? whh1f : whh1b;
    const float* BI1  = (tid < 16) ? bih1f : bih1b;
    const float* BH1  = (tid < 16) ? bhh1f : bhh1b;
    int j1 = tid & 3;
    float w1i[32], w1h[16], b1[4];
#pragma unroll
    for (int g = 0; g < 4; ++g) {
        int k = g * 4 + j1;
        b1[g] = BI1[k] + BH1[k];
#pragma unroll
        for (int m = 0; m < 8; ++m) w1i[g * 8 + m] = WIH1[k * 8 + m];
#pragma unroll
        for (int m = 0; m < 4; ++m) w1h[g * 4 + m] = WHH1[k * 4 + m];
    }

#pragma unroll
    for (int i = 0; i < 8; ++i)
        s_mean[tid + i * 32] = g_mean[blockIdx.x * 256 + tid + i * 32];
    __syncwarp();

    // ---------------- layer 0 ----------------
    {
        float hj = 0.f, cj = 0.f;
        const float* mrow = s_mean + sl * 64;
        float* hrow = s_h0[sl];
        int foff = dir * 4 + j;
        for (int st = 0; st < TSTEPS; ++st) {
            int t = dir ? (TSTEPS - 1 - st) : st;
            float xt = mrow[t];
            float h0 = __shfl_sync(0xffffffffu, hj, 0, 4);
            float h1 = __shfl_sync(0xffffffffu, hj, 1, 4);
            float h2 = __shfl_sync(0xffffffffu, hj, 2, 4);
            float h3 = __shfl_sync(0xffffffffu, hj, 3, 4);
            float ga[4];
#pragma unroll
            for (int g = 0; g < 4; ++g) {
                float p0 = fmaf(w_ih0[g], xt, b0[g]);
                p0 = fmaf(w_hh0[g * 4 + 0], h0, p0);
                float p1 = fmaf(w_hh0[g * 4 + 2], h2, w_hh0[g * 4 + 1] * h1);
                float p2 = w_hh0[g * 4 + 3] * h3;
                ga[g] = p0 + (p1 + p2);
            }
            float ig = sig_ap(ga[0]), fg = sig_ap(ga[1]);
            float gg = tanh_ap(ga[2]), og = sig_ap(ga[3]);
            cj = fmaf(fg, cj, ig * gg);
            hj = og * tanh_ap(cj);
            hrow[t * 8 + foff] = hj;
        }
    }
    __syncwarp();

    // ---------------- layer 1 ----------------
    if (tid < 16) {
        int s1 = tid >> 2;
        const float* hrow = s_h0[s1];
        float hj = 0.f, cj = 0.f;
        for (int t = 0; t < TSTEPS; ++t) {
            float4 xa = *reinterpret_cast<const float4*>(hrow + t * 8);
            float4 xb = *reinterpret_cast<const float4*>(hrow + t * 8 + 4);
            float h0 = __shfl_sync(0x0000ffffu, hj, 0, 4);
            float h1 = __shfl_sync(0x0000ffffu, hj, 1, 4);
            float h2 = __shfl_sync(0x0000ffffu, hj, 2, 4);
            float h3 = __shfl_sync(0x0000ffffu, hj, 3, 4);
            float ga[4];
#pragma unroll
            for (int g = 0; g < 4; ++g) {
                const float* wi = w1i + g * 8;
                const float* wh = w1h + g * 4;
                float p0 = fmaf(wi[0], xa.x, b1[g]);
                p0 = fmaf(wi[1], xa.y, p0);
                float p1 = fmaf(wi[3], xa.w, wi[2] * xa.z);
                float p2 = fmaf(wi[5], xb.y, wi[4] * xb.x);
                float p3 = fmaf(wi[7], xb.w, wi[6] * xb.z);
                float p4 = fmaf(wh[1], h1, wh[0] * h0);
                float p5 = fmaf(wh[3], h3, wh[2] * h2);
                ga[g] = ((p0 + p1) + (p2 + p3)) + (p4 + p5);
            }
            float ig = sig_ap(ga[0]), fg = sig_ap(ga[1]);
            float gg = tanh_ap(ga[2]), og = sig_ap(ga[3]);
            cj = fmaf(fg, cj, ig * gg);
            hj = og * tanh_ap(cj);
        }
        g_last[(blockIdx.x * 4 + s1) * 8 + j1] = hj;
    } else {
        // backward: only the first processed step (original t = T-1) is used.
        int s1 = (tid - 16) >> 2;
        const float* hrow = s_h0[s1];
        float4 xa = *reinterpret_cast<const float4*>(hrow + (TSTEPS - 1) * 8);
        float4 xb = *reinterpret_cast<const float4*>(hrow + (TSTEPS - 1) * 8 + 4);
        float ga[4];
#pragma unroll
        for (int g = 0; g < 4; ++g) {
            const float* wi = w1i + g * 8;
            float p0 = fmaf(wi[0], xa.x, b1[g]);
            p0 = fmaf(wi[1], xa.y, p0);
            float p1 = fmaf(wi[3], xa.w, wi[2] * xa.z);
            float p2 = fmaf(wi[5], xb.y, wi[4] * xb.x);
            float p3 = fmaf(wi[7], xb.w, wi[6] * xb.z);
            ga[g] = (p0 + p1) + (p2 + p3);
        }
        float cj = sig_ap(ga[0]) * tanh_ap(ga[2]);
        float hj = sig_ap(ga[3]) * tanh_ap(cj);
        g_last[(blockIdx.x * 4 + s1) * 8 + 4 + j1] = hj;
    }

    // ---------------- fc (SE MLP) in the last-arriving block ----------------
    __syncwarp();
    __shared__ unsigned s_last;
    if (tid == 0) {
        __threadfence();
        s_last = (atomicAdd(&g_ctr, 1u) == 31u);
    }
    __syncwarp();
    if (!s_last) return;
    __threadfence();  // acquire: make other blocks' g_last stores visible

    __shared__ __align__(16) float z[1024];   // [b=0 512 | b=1 512]
    __shared__ float h1s[64];                 // [b=0 32 | b=1 32]
    __shared__ float w2s[2048];               // w2 staged coalesced (64 x 32)

    // coalesced stage of z (g_last is ours, 16B-aligned) and w2 (scalar)
    {
        float4* z4 = reinterpret_cast<float4*>(z);
        const float4* gl4 = reinterpret_cast<const float4*>(g_last);
#pragma unroll
        for (int i = 0; i < 8; ++i) z4[tid + i * 32] = gl4[tid + i * 32];
#pragma unroll
        for (int i = 0; i < 64; ++i) w2s[tid + i * 32] = w2[tid + i * 32];
    }
    __syncwarp();

    // h1 = relu(z @ w1.T): cooperative coalesced GEMV (scalar loads of w1),
    // 2 rows at a time, warp-reduce.
    for (int e = 0; e < 32; e += 2) {
        const float* wr0 = w1 + e * 512;
        const float* wr1 = wr0 + 512;
        float a00 = 0.f, a01 = 0.f, a10 = 0.f, a11 = 0.f;
#pragma unroll
        for (int i = 0; i < 16; ++i) {
            int k = tid + i * 32;
            float w0 = wr0[k], w1v = wr1[k];
            float zz0 = z[k], zz1 = z[512 + k];
            a00 = fmaf(w0, zz0, a00);
            a01 = fmaf(w0, zz1, a01);
            a10 = fmaf(w1v, zz0, a10);
            a11 = fmaf(w1v, zz1, a11);
        }
#pragma unroll
        for (int off = 16; off > 0; off >>= 1) {
            a00 += __shfl_down_sync(0xffffffffu, a00, off);
            a01 += __shfl_down_sync(0xffffffffu, a01, off);
            a10 += __shfl_down_sync(0xffffffffu, a10, off);
            a11 += __shfl_down_sync(0xffffffffu, a11, off);
        }
        if (tid == 0) {
            h1s[e]          = fmaxf(a00, 0.f);
            h1s[32 + e]     = fmaxf(a01, 0.f);
            h1s[e + 1]      = fmaxf(a10, 0.f);
            h1s[32 + e + 1] = fmaxf(a11, 0.f);
        }
    }
    __syncwarp();

    // scale = sigmoid(h1 @ w2.T) from SMEM
#pragma unroll
    for (int i = 0; i < 4; ++i) {
        int idx = tid + i * 32;          // 0..127 -> (b = idx>>6, ch = idx&63)
        int b = idx >> 6, ch = idx & 63;
        const float* wr = w2s + ch * 32;
        const float* hb = h1s + b * 32;
        float acc = 0.f;
#pragma unroll
        for (int m = 0; m < 32; ++m) acc = fmaf(wr[m], hb[m], acc);
        g_scale[idx] = sig_acc(acc);
    }
    if (tid == 0) g_ctr = 0;  // reset for next graph replay
}

// ---------------------------------------------------------------------------
// Kernel 3: out = x * scale[bc]. One float4 per thread, exact grid
// (the R3-measured 86.7us configuration).
// ---------------------------------------------------------------------------
__global__ void scale_kernel(const float* __restrict__ x,
                             float* __restrict__ out) {
    unsigned v = blockIdx.x * 256u + threadIdx.x;  // < 18,874,368
    unsigned bc = v / VECS_PER_BC;                 // 0..127
    float sc = g_scale[bc];
    float4 t = reinterpret_cast<const float4*>(x)[v];
    t.x *= sc; t.y *= sc; t.z *= sc; t.w *= sc;
    __stcs(reinterpret_cast<float4*>(out) + v, t);
}

// ---------------------------------------------------------------------------
extern "C" void kernel_launch(void* const* d_in, const int* in_sizes, int n_in,
                              void* d_out, int out_size) {
    const float* x = (const float*)d_in[0];

    mean_kernel<<<8192, 256>>>(x);

    lstm_kernel<<<32, 32>>>(
        (const float*)d_in[1],  (const float*)d_in[2],
        (const float*)d_in[3],  (const float*)d_in[4],
        (const float*)d_in[5],  (const float*)d_in[6],
        (const float*)d_in[7],  (const float*)d_in[8],
        (const float*)d_in[9],  (const float*)d_in[10],
        (const float*)d_in[11], (const float*)d_in[12],
        (const float*)d_in[13], (const float*)d_in[14],
        (const float*)d_in[15], (const float*)d_in[16],
        (const float*)d_in[17], (const float*)d_in[18]);

    scale_kernel<<<73728, 256>>>(x, (float*)d_out);
}